// round 7
// baseline (speedup 1.0000x reference)
#include <cuda_runtime.h>
#include <cstdint>

#define BSZ 32
#define CIN 1024
#define P1  256
#define P3  1024
#define HH  28
#define WW  28
#define HWP 784

// ---------------- scratch (device globals; no allocation allowed) ----------
__device__ float d_xr [BSZ * CIN * HWP];  // x, tf32-rounded (GEMM-B only)
__device__ float d_y1 [BSZ * P1 * HWP];   // conv1 output (tf32-rounded, relu'd)
__device__ float d_y1s[BSZ * P1 * HWP];   // shuffled conv1 output
__device__ float d_y2 [BSZ * P1 * HWP];   // 3x3 conv output (tf32-rounded, relu'd)
__device__ float d_w1r[P1 * CIN];         // w1, tf32-rounded, [oc][cin]
__device__ float d_wd2[P1 * 9 * P1];      // wd reordered [oc][t*256+c], tf32-rounded
__device__ float d_w3r[P3 * P1];          // w3, tf32-rounded, [oc][c]

// ---------------- helpers ----------------------------------------------------
__device__ __forceinline__ float to_tf32(float x) {
    uint32_t r; asm("cvt.rna.tf32.f32 %0, %1;" : "=r"(r) : "f"(x));
    return __uint_as_float(r);
}
__device__ __forceinline__ uint32_t s2u(const void* p) {
    uint32_t a;
    asm("{ .reg .u64 t; cvta.to.shared.u64 t, %1; cvt.u32.u64 %0, t; }" : "=r"(a) : "l"(p));
    return a;
}
#define SW128(o) ((o) ^ (((o) >> 3) & 0x70))

__device__ __forceinline__ void cpa16(uint32_t dst, const void* src) {
    asm volatile("cp.async.cg.shared.global [%0], [%1], 16;" :: "r"(dst), "l"(src));
}
__device__ __forceinline__ void cpa4(uint32_t dst, const void* src, int sz) {
    asm volatile("cp.async.ca.shared.global [%0], [%1], 4, %2;"
                 :: "r"(dst), "l"(src), "r"(sz));
}
__device__ __forceinline__ void cp_commit() {
    asm volatile("cp.async.commit_group;" ::: "memory");
}
template <int N>
__device__ __forceinline__ void cp_wait() {
    asm volatile("cp.async.wait_group %0;" :: "n"(N) : "memory");
}
__device__ __forceinline__ void ldm_x4(uint32_t* r, uint32_t a) {
    asm volatile("ldmatrix.sync.aligned.m8n8.x4.shared.b16 {%0,%1,%2,%3}, [%4];"
        : "=r"(r[0]), "=r"(r[1]), "=r"(r[2]), "=r"(r[3]) : "r"(a));
}
__device__ __forceinline__ void ldm_x2(uint32_t* r, uint32_t a) {
    asm volatile("ldmatrix.sync.aligned.m8n8.x2.shared.b16 {%0,%1}, [%2];"
        : "=r"(r[0]), "=r"(r[1]) : "r"(a));
}
__device__ __forceinline__ void mma8(float* c, const uint32_t* a, const uint32_t* b) {
    asm volatile(
        "mma.sync.aligned.m16n8k8.row.col.f32.tf32.tf32.f32 "
        "{%0,%1,%2,%3}, {%4,%5,%6,%7}, {%8,%9}, {%0,%1,%2,%3};"
        : "+f"(c[0]), "+f"(c[1]), "+f"(c[2]), "+f"(c[3])
        : "r"(a[0]), "r"(a[1]), "r"(a[2]), "r"(a[3]), "r"(b[0]), "r"(b[1]));
}

// ---------------- input / weight prep ---------------------------------------
__global__ void prep_x(const float* __restrict__ x) {
    const int n4 = (BSZ * CIN * HWP) / 4;
    const float4* in = (const float4*)x;
    float4* out = (float4*)d_xr;
    for (int i = blockIdx.x * blockDim.x + threadIdx.x; i < n4;
         i += gridDim.x * blockDim.x) {
        float4 v = in[i];
        v.x = to_tf32(v.x); v.y = to_tf32(v.y);
        v.z = to_tf32(v.z); v.w = to_tf32(v.w);
        out[i] = v;
    }
}
__global__ void prep_w1(const float* __restrict__ w1) {
    int i = blockIdx.x * 256 + threadIdx.x;
    if (i < P1 * CIN) d_w1r[i] = to_tf32(w1[i]);
}
__global__ void prep_wd(const float* __restrict__ wd) {
    int i = blockIdx.x * 256 + threadIdx.x;     // [oc][c][3][3] -> [oc][t*256+c]
    if (i < P1 * P1 * 9) {
        int oc = i / (P1 * 9);
        int r  = i % (P1 * 9);
        int c  = r / 9;
        int t  = r % 9;
        d_wd2[oc * (9 * P1) + t * P1 + c] = to_tf32(wd[i]);
    }
}
__global__ void prep_w3(const float* __restrict__ w3) {
    int i = blockIdx.x * 256 + threadIdx.x;
    if (i < P3 * P1) d_w3r[i] = to_tf32(w3[i]);
}

// ---------------- per-channel spatial shuffle --------------------------------
__global__ void shuffle_dconv(const int* __restrict__ perm) {
    int plane = blockIdx.x;                 // b*256 + c
    int c = plane & (P1 - 1);
    const float* in  = d_y1  + (size_t)plane * HWP;
    float*       out = d_y1s + (size_t)plane * HWP;
    const int*   p   = perm + c * HWP;
    for (int j = threadIdx.x; j < HWP; j += 256)
        out[j] = in[p[j]];
}

// ---------------- TF32 mma.sync GEMM -----------------------------------------
// CTA tile M=128, N=112; K-chunks of 32; cp.async double buffer.
// SMEM per stage: A [128 m][32 k] (16KB) + B [112 n][32 k] (14KB), SW128 rows.
// 8 warps: warp (wm 0..3, wn 0..1) -> 32m x 56n = 2 x 7 m16n8k8 fragments.
// B operand source is resolved IN DEVICE CODE (d_xr / d_y1s / d_y2): passing a
// __device__ symbol from host code passes the host shadow address (R5/R6 bug,
// rel_err 0.74).
// SW128 is applied AFTER adding per-step k offsets (XOR sets bits 4..6; adding
// 32 to a swizzled address can carry into row bit 7).
// MODE 0: conv1  B=d_xr, M=256,  K=1024 -> tf32(relu) -> d_y1
// MODE 1: dconv  B=d_y1s implicit 3x3,   K=2304 -> tf32(relu) -> d_y2
// MODE 2: conv3  B=d_y2, M=1024, K=256  -> relu(acc + res gather) -> out
template <int MODE>
__global__ void __launch_bounds__(256, 2)
mma_gemm(float* __restrict__ Outx,
         const float* __restrict__ Res, const int* __restrict__ Perm)
{
    constexpr int M   = (MODE == 2) ? P3 : P1;
    constexpr int K   = (MODE == 0) ? CIN : (MODE == 1 ? 2304 : P1);
    constexpr int NCH = K / 32;
    constexpr int CB  = (MODE == 1) ? P1 : K;
    constexpr uint32_t STG = 30720u;        // 16KB A + 14KB B per stage

    const float* A   = (MODE == 0) ? d_w1r : (MODE == 1 ? d_wd2 : d_w3r);
    const float* Bg  = (MODE == 0) ? d_xr  : (MODE == 1 ? d_y1s : d_y2);
    float*       Out = (MODE == 2) ? Outx  : (MODE == 0 ? d_y1 : d_y2);

    const int b   = blockIdx.z;
    const int m0  = blockIdx.y * 128;
    const int n0  = blockIdx.x * 112;
    const int tid = threadIdx.x;
    const int wid = tid >> 5;
    const int lid = tid & 31;
    const int wm  = wid & 3;
    const int wn  = wid >> 2;

    extern __shared__ char smem[];
    const uint32_t sb = (s2u(smem) + 1023u) & ~1023u;

    const float* Bb  = Bg + (size_t)b * CB * HWP;
    const float* Ag0 = A + (size_t)m0 * K;

    // per-lane row byte-offsets (pre-swizzle; swizzle applied at each use)
    const uint32_t roA  = (uint32_t)((wm * 32 + (lid & 15)) * 128 + (lid >> 4) * 16);
    const uint32_t roB4 = (uint32_t)((wn * 56 + (lid >> 4) * 8 + (lid & 7)) * 128 +
                                     ((lid >> 3) & 1) * 16);
    const uint32_t roB2 = (uint32_t)((wn * 56 + 48 + (lid & 7)) * 128 +
                                     ((lid >> 3) & 1) * 16);

    float acc[2][7][4];
    #pragma unroll
    for (int i = 0; i < 2; i++)
        #pragma unroll
        for (int j = 0; j < 7; j++)
            #pragma unroll
            for (int q = 0; q < 4; q++) acc[i][j][q] = 0.0f;

    auto load_chunk = [&](int st, int ch) {
        const uint32_t As = sb + (uint32_t)st * STG;
        const uint32_t Bs = As + 16384u;
        const int k0 = ch * 32;
        // A tile: 1024 float4
        const float* Ag = Ag0 + k0;
        #pragma unroll
        for (int i = 0; i < 4; i++) {
            int idx = tid + i * 256;
            int r = idx >> 3, q = idx & 7;
            cpa16(As + SW128((uint32_t)(r * 128 + q * 16)), Ag + (size_t)r * K + q * 4);
        }
        // B tile: 3584 scalars, transposed into [n][k] rows
        if (MODE == 1) {
            const int t  = k0 >> 8;
            const int dy = t / 3 - 1, dx = t - (t / 3) * 3 - 1;
            const int cb = k0 & 255;
            #pragma unroll
            for (int i = 0; i < 14; i++) {
                int idx = tid + i * 256;
                int k = idx / 112, nl = idx - k * 112;
                int n = n0 + nl;
                int h = n / WW, w = n - h * WW;
                int hh = h + dy, ww = w + dx;
                bool ok = ((unsigned)hh < (unsigned)HH) && ((unsigned)ww < (unsigned)WW);
                const float* src = ok ? (Bb + (size_t)(cb + k) * HWP + hh * WW + ww) : Bb;
                cpa4(Bs + SW128((uint32_t)(nl * 128 + k * 4)), src, ok ? 4 : 0);
            }
        } else {
            #pragma unroll
            for (int i = 0; i < 14; i++) {
                int idx = tid + i * 256;
                int k = idx / 112, nl = idx - k * 112;
                cpa4(Bs + SW128((uint32_t)(nl * 128 + k * 4)),
                     Bb + (size_t)(k0 + k) * HWP + n0 + nl, 4);
            }
        }
    };

    auto compute = [&](int st) {
        const uint32_t As = sb + (uint32_t)st * STG;
        const uint32_t Bs = As + 16384u;
        #pragma unroll
        for (int s = 0; s < 4; s++) {
            uint32_t af[2][4];
            ldm_x4(af[0], As + SW128(roA + s * 32));
            ldm_x4(af[1], As + SW128(roA + 2048u + s * 32));
            uint32_t bf[7][2];
            #pragma unroll
            for (int j = 0; j < 3; j++) {
                uint32_t r4[4];
                ldm_x4(r4, Bs + SW128(roB4 + (uint32_t)j * 2048u + s * 32));
                bf[2 * j][0] = r4[0]; bf[2 * j][1] = r4[1];
                bf[2 * j + 1][0] = r4[2]; bf[2 * j + 1][1] = r4[3];
            }
            ldm_x2(bf[6], Bs + SW128(roB2 + s * 32));
            #pragma unroll
            for (int mi = 0; mi < 2; mi++)
                #pragma unroll
                for (int ni = 0; ni < 7; ni++)
                    mma8(acc[mi][ni], af[mi], bf[ni]);
        }
    };

    // ---- pipelined mainloop ----
    load_chunk(0, 0);
    cp_commit();
    for (int ch = 0; ch < NCH; ch++) {
        if (ch + 1 < NCH) {
            load_chunk((ch + 1) & 1, ch + 1);
            cp_commit();
            cp_wait<1>();
        } else {
            cp_wait<0>();
        }
        __syncthreads();
        compute(ch & 1);
        __syncthreads();
    }

    // ---- epilogue ----
    const int gid = lid >> 2, tig = lid & 3;
    #pragma unroll
    for (int mi = 0; mi < 2; mi++) {
        const int m = m0 + wm * 32 + mi * 16 + gid;
        float* row0 = Out + ((size_t)b * M + m) * HWP + n0 + wn * 56;
        float* row1 = row0 + 8 * HWP;
        const float* rr0 = nullptr; const float* rr1 = nullptr;
        const int* pp0 = nullptr; const int* pp1 = nullptr;
        if (MODE == 2) {
            rr0 = Res + ((size_t)b * CIN + m) * HWP;
            rr1 = rr0 + 8 * HWP;
            pp0 = Perm + (size_t)m * HWP;
            pp1 = pp0 + 8 * HWP;
        }
        #pragma unroll
        for (int ni = 0; ni < 7; ni++) {
            const int noff = ni * 8 + tig * 2;
            float v0 = acc[mi][ni][0], v1 = acc[mi][ni][1];
            float v2 = acc[mi][ni][2], v3 = acc[mi][ni][3];
            if (MODE == 2) {
                const int gn = n0 + wn * 56 + noff;
                v0 += __ldg(rr0 + __ldg(pp0 + gn));
                v1 += __ldg(rr0 + __ldg(pp0 + gn + 1));
                v2 += __ldg(rr1 + __ldg(pp1 + gn));
                v3 += __ldg(rr1 + __ldg(pp1 + gn + 1));
            }
            v0 = fmaxf(v0, 0.f); v1 = fmaxf(v1, 0.f);
            v2 = fmaxf(v2, 0.f); v3 = fmaxf(v3, 0.f);
            if (MODE != 2) {
                // round intermediates so the next GEMM sees rna-tf32 activations
                v0 = to_tf32(v0); v1 = to_tf32(v1);
                v2 = to_tf32(v2); v3 = to_tf32(v3);
            }
            *(float2*)(row0 + noff) = make_float2(v0, v1);
            *(float2*)(row1 + noff) = make_float2(v2, v3);
        }
    }
}

// ---------------- launch ----------------------------------------------------
extern "C" void kernel_launch(void* const* d_in, const int* in_sizes, int n_in,
                              void* d_out, int out_size)
{
    const float* x  = (const float*)d_in[0];
    const float* w1 = (const float*)d_in[1];
    const float* wd = (const float*)d_in[2];
    const float* w3 = (const float*)d_in[3];
    const int*   pd = (const int*)d_in[4];
    const int*   pr = (const int*)d_in[5];
    float* out = (float*)d_out;

    const int SMEMB = 2 * 30720 + 1024;

    cudaFuncSetAttribute(mma_gemm<0>, cudaFuncAttributeMaxDynamicSharedMemorySize, SMEMB);
    cudaFuncSetAttribute(mma_gemm<1>, cudaFuncAttributeMaxDynamicSharedMemorySize, SMEMB);
    cudaFuncSetAttribute(mma_gemm<2>, cudaFuncAttributeMaxDynamicSharedMemorySize, SMEMB);

    prep_x<<<4096, 256>>>(x);
    prep_w1<<<(P1 * CIN + 255) / 256, 256>>>(w1);
    prep_wd<<<(P1 * P1 * 9 + 255) / 256, 256>>>(wd);
    prep_w3<<<(P3 * P1 + 255) / 256, 256>>>(w3);

    dim3 blk(256);
    dim3 g1(7, 2, BSZ);
    dim3 g3(7, 8, BSZ);

    mma_gemm<0><<<g1, blk, SMEMB>>>(nullptr, nullptr, nullptr);
    shuffle_dconv<<<BSZ * P1, 256>>>(pd);
    mma_gemm<1><<<g1, blk, SMEMB>>>(nullptr, nullptr, nullptr);
    mma_gemm<2><<<g3, blk, SMEMB>>>(out, x, pr);
}

// round 8
// speedup vs baseline: 1.0516x; 1.0516x over previous
#include <cuda_runtime.h>
#include <cstdint>

#define BSZ 32
#define CIN 1024
#define P1  256
#define P3  1024
#define HH  28
#define WW  28
#define HWP 784

// ---------------- scratch (device globals; no allocation allowed) ----------
__device__ float d_xr [BSZ * CIN * HWP];  // x, tf32-rounded (GEMM-B only)
__device__ float d_y1 [BSZ * P1 * HWP];   // conv1 output (tf32-rounded, relu'd)
__device__ float d_y1s[BSZ * P1 * HWP];   // shuffled conv1 output
__device__ float d_y2 [BSZ * P1 * HWP];   // 3x3 conv output (tf32-rounded, relu'd)
__device__ float d_w1r[P1 * CIN];         // w1, tf32-rounded, [oc][cin]
__device__ float d_wd2[P1 * 9 * P1];      // wd reordered [oc][t*256+c], tf32-rounded
__device__ float d_w3r[P3 * P1];          // w3, tf32-rounded, [oc][c]

// ---------------- helpers ----------------------------------------------------
__device__ __forceinline__ float to_tf32(float x) {
    uint32_t r; asm("cvt.rna.tf32.f32 %0, %1;" : "=r"(r) : "f"(x));
    return __uint_as_float(r);
}
__device__ __forceinline__ uint32_t s2u(const void* p) {
    uint32_t a;
    asm("{ .reg .u64 t; cvta.to.shared.u64 t, %1; cvt.u32.u64 %0, t; }" : "=r"(a) : "l"(p));
    return a;
}
#define SW128(o) ((o) ^ (((o) >> 3) & 0x70))

__device__ __forceinline__ void cpa16(uint32_t dst, const void* src) {
    asm volatile("cp.async.cg.shared.global [%0], [%1], 16;" :: "r"(dst), "l"(src));
}
__device__ __forceinline__ void cpa4(uint32_t dst, const void* src, int sz) {
    asm volatile("cp.async.ca.shared.global [%0], [%1], 4, %2;"
                 :: "r"(dst), "l"(src), "r"(sz));
}
__device__ __forceinline__ void cp_commit() {
    asm volatile("cp.async.commit_group;" ::: "memory");
}
template <int N>
__device__ __forceinline__ void cp_wait() {
    asm volatile("cp.async.wait_group %0;" :: "n"(N) : "memory");
}
__device__ __forceinline__ void ldm_x4(uint32_t* r, uint32_t a) {
    asm volatile("ldmatrix.sync.aligned.m8n8.x4.shared.b16 {%0,%1,%2,%3}, [%4];"
        : "=r"(r[0]), "=r"(r[1]), "=r"(r[2]), "=r"(r[3]) : "r"(a));
}
__device__ __forceinline__ void ldm_x2(uint32_t* r, uint32_t a) {
    asm volatile("ldmatrix.sync.aligned.m8n8.x2.shared.b16 {%0,%1}, [%2];"
        : "=r"(r[0]), "=r"(r[1]) : "r"(a));
}
__device__ __forceinline__ void mma8(float* c, const uint32_t* a, const uint32_t* b) {
    asm volatile(
        "mma.sync.aligned.m16n8k8.row.col.f32.tf32.tf32.f32 "
        "{%0,%1,%2,%3}, {%4,%5,%6,%7}, {%8,%9}, {%0,%1,%2,%3};"
        : "+f"(c[0]), "+f"(c[1]), "+f"(c[2]), "+f"(c[3])
        : "r"(a[0]), "r"(a[1]), "r"(a[2]), "r"(a[3]), "r"(b[0]), "r"(b[1]));
}

// ---------------- input / weight prep ---------------------------------------
__global__ void prep_x(const float* __restrict__ x) {
    const int n4 = (BSZ * CIN * HWP) / 4;
    const float4* in = (const float4*)x;
    float4* out = (float4*)d_xr;
    for (int i = blockIdx.x * blockDim.x + threadIdx.x; i < n4;
         i += gridDim.x * blockDim.x) {
        float4 v = in[i];
        v.x = to_tf32(v.x); v.y = to_tf32(v.y);
        v.z = to_tf32(v.z); v.w = to_tf32(v.w);
        out[i] = v;
    }
}
__global__ void prep_w1(const float* __restrict__ w1) {
    int i = blockIdx.x * 256 + threadIdx.x;
    if (i < P1 * CIN) d_w1r[i] = to_tf32(w1[i]);
}
__global__ void prep_wd(const float* __restrict__ wd) {
    int i = blockIdx.x * 256 + threadIdx.x;     // [oc][c][3][3] -> [oc][t*256+c]
    if (i < P1 * P1 * 9) {
        int oc = i / (P1 * 9);
        int r  = i % (P1 * 9);
        int c  = r / 9;
        int t  = r % 9;
        d_wd2[oc * (9 * P1) + t * P1 + c] = to_tf32(wd[i]);
    }
}
__global__ void prep_w3(const float* __restrict__ w3) {
    int i = blockIdx.x * 256 + threadIdx.x;
    if (i < P3 * P1) d_w3r[i] = to_tf32(w3[i]);
}

// ---------------- per-channel spatial shuffle --------------------------------
__global__ void shuffle_dconv(const int* __restrict__ perm) {
    int plane = blockIdx.x;                 // b*256 + c
    int c = plane & (P1 - 1);
    const float* in  = d_y1  + (size_t)plane * HWP;
    float*       out = d_y1s + (size_t)plane * HWP;
    const int*   p   = perm + c * HWP;
    for (int j = threadIdx.x; j < HWP; j += 256)
        out[j] = in[p[j]];
}

// ---------------- TF32 mma.sync GEMM -----------------------------------------
// CTA tile M=128, N=112; K-chunks of 32; 3-stage cp.async pipeline with ONE
// __syncthreads per iteration (wait ch -> sync -> issue ch+2 -> compute ch;
// slots distinct mod 3, overwritten slot held ch-1 which the sync protects).
// A commit is issued EVERY iteration (possibly empty) so cp.wait_group<1>
// always retires exactly group ch.
// SMEM per stage: A [128 m][32 k] (16KB) + B [112 n][32 k] (14KB), SW128 rows.
// 8 warps: warp (wm 0..3, wn 0..1) -> 32m x 56n = 2 x 7 m16n8k8 fragments.
// B operand source resolved IN DEVICE CODE (host-side __device__ symbol would
// pass the shadow address — R5/R6 bug).
// SW128 applied AFTER adding per-step k offsets (XOR sets bits 4..6).
// MODE 0: conv1  B=d_xr, M=256,  K=1024 -> tf32(relu) -> d_y1
// MODE 1: dconv  B=d_y1s implicit 3x3,   K=2304 -> tf32(relu) -> d_y2
// MODE 2: conv3  B=d_y2, M=1024, K=256  -> relu(acc + res gather) -> out
template <int MODE>
__global__ void __launch_bounds__(256)
mma_gemm(float* __restrict__ Outx,
         const float* __restrict__ Res, const int* __restrict__ Perm)
{
    constexpr int M   = (MODE == 2) ? P3 : P1;
    constexpr int K   = (MODE == 0) ? CIN : (MODE == 1 ? 2304 : P1);
    constexpr int NCH = K / 32;
    constexpr int CB  = (MODE == 1) ? P1 : K;
    constexpr uint32_t STG = 30720u;        // 16KB A + 14KB B per stage

    const float* A   = (MODE == 0) ? d_w1r : (MODE == 1 ? d_wd2 : d_w3r);
    const float* Bg  = (MODE == 0) ? d_xr  : (MODE == 1 ? d_y1s : d_y2);
    float*       Out = (MODE == 2) ? Outx  : (MODE == 0 ? d_y1 : d_y2);

    const int b   = blockIdx.z;
    const int m0  = blockIdx.y * 128;
    const int n0  = blockIdx.x * 112;
    const int tid = threadIdx.x;
    const int wid = tid >> 5;
    const int lid = tid & 31;
    const int wm  = wid & 3;
    const int wn  = wid >> 2;

    extern __shared__ char smem[];
    const uint32_t sb = (s2u(smem) + 1023u) & ~1023u;

    const float* Bb  = Bg + (size_t)b * CB * HWP;
    const float* Ag0 = A + (size_t)m0 * K;

    // per-lane row byte-offsets (pre-swizzle; swizzle applied at each use)
    const uint32_t roA  = (uint32_t)((wm * 32 + (lid & 15)) * 128 + (lid >> 4) * 16);
    const uint32_t roB4 = (uint32_t)((wn * 56 + (lid >> 4) * 8 + (lid & 7)) * 128 +
                                     ((lid >> 3) & 1) * 16);
    const uint32_t roB2 = (uint32_t)((wn * 56 + 48 + (lid & 7)) * 128 +
                                     ((lid >> 3) & 1) * 16);

    float acc[2][7][4];
    #pragma unroll
    for (int i = 0; i < 2; i++)
        #pragma unroll
        for (int j = 0; j < 7; j++)
            #pragma unroll
            for (int q = 0; q < 4; q++) acc[i][j][q] = 0.0f;

    auto load_chunk = [&](int st, int ch) {
        const uint32_t As = sb + (uint32_t)st * STG;
        const uint32_t Bs = As + 16384u;
        const int k0 = ch * 32;
        // A tile: 1024 float4
        const float* Ag = Ag0 + k0;
        #pragma unroll
        for (int i = 0; i < 4; i++) {
            int idx = tid + i * 256;
            int r = idx >> 3, q = idx & 7;
            cpa16(As + SW128((uint32_t)(r * 128 + q * 16)), Ag + (size_t)r * K + q * 4);
        }
        // B tile: 3584 scalars, transposed into [n][k] rows
        if (MODE == 1) {
            const int t  = k0 >> 8;
            const int dy = t / 3 - 1, dx = t - (t / 3) * 3 - 1;
            const int cb = k0 & 255;
            #pragma unroll
            for (int i = 0; i < 14; i++) {
                int idx = tid + i * 256;
                int k = idx / 112, nl = idx - k * 112;
                int n = n0 + nl;
                int h = n / WW, w = n - h * WW;
                int hh = h + dy, ww = w + dx;
                bool ok = ((unsigned)hh < (unsigned)HH) && ((unsigned)ww < (unsigned)WW);
                const float* src = ok ? (Bb + (size_t)(cb + k) * HWP + hh * WW + ww) : Bb;
                cpa4(Bs + SW128((uint32_t)(nl * 128 + k * 4)), src, ok ? 4 : 0);
            }
        } else {
            #pragma unroll
            for (int i = 0; i < 14; i++) {
                int idx = tid + i * 256;
                int k = idx / 112, nl = idx - k * 112;
                cpa4(Bs + SW128((uint32_t)(nl * 128 + k * 4)),
                     Bb + (size_t)(k0 + k) * HWP + n0 + nl, 4);
            }
        }
    };

    auto compute = [&](int st) {
        const uint32_t As = sb + (uint32_t)st * STG;
        const uint32_t Bs = As + 16384u;
        #pragma unroll
        for (int s = 0; s < 4; s++) {
            uint32_t af[2][4];
            ldm_x4(af[0], As + SW128(roA + s * 32));
            ldm_x4(af[1], As + SW128(roA + 2048u + s * 32));
            uint32_t bf[7][2];
            #pragma unroll
            for (int j = 0; j < 3; j++) {
                uint32_t r4[4];
                ldm_x4(r4, Bs + SW128(roB4 + (uint32_t)j * 2048u + s * 32));
                bf[2 * j][0] = r4[0]; bf[2 * j][1] = r4[1];
                bf[2 * j + 1][0] = r4[2]; bf[2 * j + 1][1] = r4[3];
            }
            ldm_x2(bf[6], Bs + SW128(roB2 + s * 32));
            #pragma unroll
            for (int mi = 0; mi < 2; mi++)
                #pragma unroll
                for (int ni = 0; ni < 7; ni++)
                    mma8(acc[mi][ni], af[mi], bf[ni]);
        }
    };

    // ---- 3-stage pipelined mainloop, one barrier per iteration ----
    load_chunk(0, 0);
    cp_commit();
    load_chunk(1, 1);
    cp_commit();
    int slot = 2;                       // (ch+2) % 3, starting at ch=0
    for (int ch = 0; ch < NCH; ch++) {
        cp_wait<1>();                   // group ch complete (ch+1 may be pending)
        __syncthreads();                // data visible + all warps done with ch-1
        if (ch + 2 < NCH) load_chunk(slot, ch + 2);
        cp_commit();                    // always commit (empty at tail) to keep
                                        // the pending-group count invariant
        compute(ch % 3);
        slot = (slot == 2) ? 0 : slot + 1;
    }

    // ---- epilogue ----
    const int gid = lid >> 2, tig = lid & 3;
    #pragma unroll
    for (int mi = 0; mi < 2; mi++) {
        const int m = m0 + wm * 32 + mi * 16 + gid;
        float* row0 = Out + ((size_t)b * M + m) * HWP + n0 + wn * 56;
        float* row1 = row0 + 8 * HWP;
        const float* rr0 = nullptr; const float* rr1 = nullptr;
        const int* pp0 = nullptr; const int* pp1 = nullptr;
        if (MODE == 2) {
            rr0 = Res + ((size_t)b * CIN + m) * HWP;
            rr1 = rr0 + 8 * HWP;
            pp0 = Perm + (size_t)m * HWP;
            pp1 = pp0 + 8 * HWP;
        }
        #pragma unroll
        for (int ni = 0; ni < 7; ni++) {
            const int noff = ni * 8 + tig * 2;
            float v0 = acc[mi][ni][0], v1 = acc[mi][ni][1];
            float v2 = acc[mi][ni][2], v3 = acc[mi][ni][3];
            if (MODE == 2) {
                const int gn = n0 + wn * 56 + noff;
                v0 += __ldg(rr0 + __ldg(pp0 + gn));
                v1 += __ldg(rr0 + __ldg(pp0 + gn + 1));
                v2 += __ldg(rr1 + __ldg(pp1 + gn));
                v3 += __ldg(rr1 + __ldg(pp1 + gn + 1));
            }
            v0 = fmaxf(v0, 0.f); v1 = fmaxf(v1, 0.f);
            v2 = fmaxf(v2, 0.f); v3 = fmaxf(v3, 0.f);
            if (MODE != 2) {
                // round intermediates so the next GEMM sees rna-tf32 activations
                v0 = to_tf32(v0); v1 = to_tf32(v1);
                v2 = to_tf32(v2); v3 = to_tf32(v3);
            }
            *(float2*)(row0 + noff) = make_float2(v0, v1);
            *(float2*)(row1 + noff) = make_float2(v2, v3);
        }
    }
}

// ---------------- launch ----------------------------------------------------
extern "C" void kernel_launch(void* const* d_in, const int* in_sizes, int n_in,
                              void* d_out, int out_size)
{
    const float* x  = (const float*)d_in[0];
    const float* w1 = (const float*)d_in[1];
    const float* wd = (const float*)d_in[2];
    const float* w3 = (const float*)d_in[3];
    const int*   pd = (const int*)d_in[4];
    const int*   pr = (const int*)d_in[5];
    float* out = (float*)d_out;

    const int SMEMB = 3 * 30720 + 1024;   // 3 stages + align pad

    cudaFuncSetAttribute(mma_gemm<0>, cudaFuncAttributeMaxDynamicSharedMemorySize, SMEMB);
    cudaFuncSetAttribute(mma_gemm<1>, cudaFuncAttributeMaxDynamicSharedMemorySize, SMEMB);
    cudaFuncSetAttribute(mma_gemm<2>, cudaFuncAttributeMaxDynamicSharedMemorySize, SMEMB);

    prep_x<<<4096, 256>>>(x);
    prep_w1<<<(P1 * CIN + 255) / 256, 256>>>(w1);
    prep_wd<<<(P1 * P1 * 9 + 255) / 256, 256>>>(wd);
    prep_w3<<<(P3 * P1 + 255) / 256, 256>>>(w3);

    dim3 blk(256);
    dim3 g1(7, 2, BSZ);
    dim3 g3(7, 8, BSZ);

    mma_gemm<0><<<g1, blk, SMEMB>>>(nullptr, nullptr, nullptr);
    shuffle_dconv<<<BSZ * P1, 256>>>(pd);
    mma_gemm<1><<<g1, blk, SMEMB>>>(nullptr, nullptr, nullptr);
    mma_gemm<2><<<g3, blk, SMEMB>>>(out, x, pr);
}